// round 3
// baseline (speedup 1.0000x reference)
#include <cuda_runtime.h>
#include <cuda_bf16.h>

#define LOG2E 1.4426950408889634f
typedef unsigned long long u64;

// ---------------- scratch (__device__ globals; no allocation allowed) -------
__device__ float g_xn  [32*1024*64];
__device__ float g_xi  [32*1024*128];
__device__ float g_z   [32*1024*128];
__device__ float g_xc  [32*1024*128];
__device__ float g_dt  [32*1024*128];
__device__ float g_Bm  [32*1024*16];
__device__ float g_Cm  [32*1024*16];
__device__ float g_y   [32*1024*128];
__device__ float g_pend[32*8*128*16];
__device__ float g_dtot[32*8*128*16];
__device__ float g_h0  [32*8*128*16];

__device__ __forceinline__ float ex2f(float x) {
    float r; asm("ex2.approx.f32 %0, %1;" : "=f"(r) : "f"(x)); return r;
}
__device__ __forceinline__ float siluf(float x) {
    return x / (1.0f + __expf(-x));
}
// ---- packed f32x2 helpers (2 lanes per fma-pipe instruction) ----
__device__ __forceinline__ u64 pack2(float x, float y) {
    u64 r; asm("mov.b64 %0, {%1, %2};" : "=l"(r) : "f"(x), "f"(y)); return r;
}
__device__ __forceinline__ void unpack2(u64 v, float& x, float& y) {
    asm("mov.b64 {%0, %1}, %2;" : "=f"(x), "=f"(y) : "l"(v));
}
__device__ __forceinline__ u64 fma2(u64 a, u64 b, u64 c) {
    u64 d; asm("fma.rn.f32x2 %0, %1, %2, %3;" : "=l"(d) : "l"(a), "l"(b), "l"(c)); return d;
}
__device__ __forceinline__ u64 mul2(u64 a, u64 b) {
    u64 d; asm("mul.rn.f32x2 %0, %1, %2;" : "=l"(d) : "l"(a), "l"(b)); return d;
}

// ======================= K1: LayerNorm + W_in GEMM ==========================
// grid = 32 seq * 32 tiles (32 tokens each), block = 128
__global__ void __launch_bounds__(128) k1_ln_inproj(
    const float* __restrict__ x0, const float* __restrict__ x1,
    const float* __restrict__ x2, const float* __restrict__ x3,
    const float* __restrict__ ga, const float* __restrict__ gb,
    const float* __restrict__ gc, const float* __restrict__ gd,
    const float* __restrict__ ba, const float* __restrict__ bb,
    const float* __restrict__ bc_, const float* __restrict__ bd,
    const float* __restrict__ W_in)
{
    __shared__ float xs[32*66];     // [t][c], pitch 66 (8B-aligned rows)
    __shared__ float Wsh[128*66];   // [j][k], pitch 66
    __shared__ float stat[64];

    int tid = threadIdx.x;
    int blk = blockIdx.x;
    int seq = blk >> 5;
    int l0  = (blk & 31) * 32;
    int br  = seq >> 3;
    int b   = seq & 7;

    const float* xp = (br == 0) ? x0 : (br == 1) ? x1 : (br == 2) ? x2 : x3;
    const float* gp = (br == 0) ? ga : (br == 1) ? gb : (br == 2) ? gc : gd;
    const float* bp = (br == 0) ? ba : (br == 1) ? bb : (br == 2) ? bc_ : bd;

    for (int idx = tid; idx < 2048; idx += 128) {
        int c = idx >> 5, t = idx & 31;
        xs[t*66 + c] = xp[(size_t)(b*64 + c)*1024 + l0 + t];
    }
    __syncthreads();
    if (tid < 32) {
        float s = 0.f, s2 = 0.f;
        #pragma unroll 8
        for (int c = 0; c < 64; c++) { float v = xs[tid*66 + c]; s += v; s2 += v*v; }
        float m = s * (1.0f/64.0f);
        float var = s2 * (1.0f/64.0f) - m*m;
        stat[tid*2]   = m;
        stat[tid*2+1] = rsqrtf(var + 1e-5f);
    }
    __syncthreads();
    for (int idx = tid; idx < 2048; idx += 128) {
        int c = idx & 63, t = idx >> 6;
        float v = (xs[t*66 + c] - stat[t*2]) * stat[t*2+1] * gp[c] + bp[c];
        xs[t*66 + c] = v;
        g_xn[(size_t)(seq*1024 + l0 + t)*64 + c] = v;
    }

    // GEMM: two halves of the 256 outputs (xi then z), f32x2-packed over k
    int tg = tid >> 4;      // 8 token groups of 4 tokens
    int jg = tid & 15;      // outputs jg + 16u, u = 0..7
    for (int h = 0; h < 2; h++) {
        __syncthreads();
        for (int idx = tid; idx < 8192; idx += 128) {
            int c = idx & 63, jj = idx >> 6;
            Wsh[jj*66 + c] = W_in[(size_t)(h*128 + jj)*64 + c];
        }
        __syncthreads();
        u64 acc2[4][8];
        #pragma unroll
        for (int i = 0; i < 4; i++)
            #pragma unroll
            for (int u = 0; u < 8; u++) acc2[i][u] = 0ull;
        #pragma unroll 4
        for (int k2 = 0; k2 < 32; k2++) {
            u64 xv2[4], w2[8];
            #pragma unroll
            for (int i = 0; i < 4; i++)
                xv2[i] = *(const u64*)&xs[(tg*4 + i)*66 + 2*k2];
            #pragma unroll
            for (int u = 0; u < 8; u++)
                w2[u] = *(const u64*)&Wsh[(jg + 16*u)*66 + 2*k2];
            #pragma unroll
            for (int u = 0; u < 8; u++)
                #pragma unroll
                for (int i = 0; i < 4; i++)
                    acc2[i][u] = fma2(xv2[i], w2[u], acc2[i][u]);
        }
        float* dst = (h == 0) ? g_xi : g_z;
        #pragma unroll
        for (int i = 0; i < 4; i++) {
            int t = tg*4 + i;
            #pragma unroll
            for (int u = 0; u < 8; u++) {
                float lo, hi; unpack2(acc2[i][u], lo, hi);
                dst[(size_t)(seq*1024 + l0 + t)*128 + jg + 16*u] = lo + hi;
            }
        }
    }
}

// ============ K2: causal conv4 + SiLU + x_proj GEMM + dt(softplus) ==========
// grid = 32 seq * 32 tiles (32 tokens), block = 128 (thread = channel d)
__global__ void __launch_bounds__(128) k2_conv_proj(
    const float* __restrict__ W_conv, const float* __restrict__ b_conv,
    const float* __restrict__ W_xproj, const float* __restrict__ W_dt,
    const float* __restrict__ b_dt)
{
    __shared__ float bufA[37*128];   // xi halo tile [35][128], then W_xproj^T [128][37]
    __shared__ float xcs[32*128];
    __shared__ float res36[32*36];

    int tid = threadIdx.x;
    int blk = blockIdx.x;
    int seq = blk >> 5;
    int l0  = (blk & 31) * 32;

    for (int idx = tid; idx < 35*128; idx += 128) {
        int row = idx >> 7, dd = idx & 127;
        int tl = l0 - 3 + row;
        bufA[row*128 + dd] = (tl >= 0) ? g_xi[(size_t)(seq*1024 + tl)*128 + dd] : 0.f;
    }
    __syncthreads();

    int d = tid;
    float wc0 = W_conv[d*4+0], wc1 = W_conv[d*4+1], wc2 = W_conv[d*4+2], wc3 = W_conv[d*4+3];
    float bcv = b_conv[d];
    #pragma unroll 4
    for (int t = 0; t < 32; t++) {
        float v = bcv + wc0*bufA[t*128 + d] + wc1*bufA[(t+1)*128 + d]
                      + wc2*bufA[(t+2)*128 + d] + wc3*bufA[(t+3)*128 + d];
        v = siluf(v);
        xcs[t*128 + d] = v;
        g_xc[(size_t)(seq*1024 + l0 + t)*128 + d] = v;
    }
    __syncthreads();
    for (int idx = tid; idx < 36*128; idx += 128) {
        int dd = idx & 127, j = idx >> 7;
        bufA[dd*37 + j] = W_xproj[(size_t)j*128 + dd];
    }
    __syncthreads();
    for (int p = tid; p < 576; p += 128) {
        int tok = p / 18;
        int j0 = (p - tok*18) * 2;
        float a0 = 0.f, a1 = 0.f;
        #pragma unroll 16
        for (int dd = 0; dd < 128; dd++) {
            float xv = xcs[tok*128 + dd];
            a0 = fmaf(xv, bufA[dd*37 + j0],     a0);
            a1 = fmaf(xv, bufA[dd*37 + j0 + 1], a1);
        }
        res36[tok*36 + j0]     = a0;
        res36[tok*36 + j0 + 1] = a1;
    }
    __syncthreads();
    float wd0 = W_dt[d*4+0], wd1 = W_dt[d*4+1], wd2 = W_dt[d*4+2], wd3 = W_dt[d*4+3];
    float bdv = b_dt[d];
    #pragma unroll 4
    for (int t = 0; t < 32; t++) {
        float raw = bdv + wd0*res36[t*36+0] + wd1*res36[t*36+1]
                        + wd2*res36[t*36+2] + wd3*res36[t*36+3];
        float sp = fmaxf(raw, 0.f) + log1pf(__expf(-fabsf(raw)));
        g_dt[(size_t)(seq*1024 + l0 + t)*128 + d] = sp;
    }
    for (int idx = tid; idx < 1024; idx += 128) {
        int tok = idx >> 5, q = idx & 31;
        float v = res36[tok*36 + 4 + q];
        if (q < 16) g_Bm[(size_t)(seq*1024 + l0 + tok)*16 + q]        = v;
        else        g_Cm[(size_t)(seq*1024 + l0 + tok)*16 + (q - 16)] = v;
    }
}

// helper: detect a2[s] == (s+1)*a2[0] (true for this problem's A_log)
__device__ __forceinline__ bool ratio_fast(const float* a2) {
    bool ok = true;
    #pragma unroll
    for (int s = 1; s < 16; s++) {
        float want = (float)(s + 1) * a2[0];
        ok = ok && (fabsf(a2[s] - want) <= 1e-3f * fabsf(want));
    }
    return ok;
}

// ============== K3: per-chunk scan summaries (h0 = 0) =======================
// grid = 256 (seq*8 + chunk), block = 128 (thread = channel d)
__global__ void __launch_bounds__(128) k3_chunk(const float* __restrict__ A_log)
{
    __shared__ float Bs[128*16];
    int tid = threadIdx.x;
    int blk = blockIdx.x;
    int seq = blk >> 3;
    int ck  = blk & 7;
    int c0  = ck * 128;

    for (int idx = tid; idx < 2048; idx += 128)
        Bs[idx] = g_Bm[(size_t)(seq*1024 + c0)*16 + idx];
    __syncthreads();

    int d = tid;
    float a2[16];
    #pragma unroll
    for (int s = 0; s < 16; s++) a2[s] = -__expf(A_log[d*16 + s]) * LOG2E;
    bool fast = ratio_fast(a2);

    const float* dtp_ = g_dt + (size_t)(seq*1024 + c0)*128 + d;
    const float* xcp_ = g_xc + (size_t)(seq*1024 + c0)*128 + d;
    float sdt = 0.f;

    if (fast) {
        const u64* B2 = (const u64*)Bs;
        u64 h2[8];
        #pragma unroll
        for (int j = 0; j < 8; j++) h2[j] = 0ull;
        float dtv = dtp_[0], xcv = xcp_[0];
        for (int t = 0; t < 128; t++) {
            float ndt = 0.f, nxc = 0.f;
            if (t < 127) { ndt = dtp_[(t+1)*128]; nxc = xcp_[(t+1)*128]; }
            sdt += dtv;
            float dx = dtv * xcv;
            u64 dx2 = pack2(dx, dx);
            float p = ex2f(dtv * a2[0]);
            float psq = p * p;
            u64 q  = pack2(psq, psq);
            u64 dA = pack2(p, psq);
            #pragma unroll
            for (int j = 0; j < 8; j++) {
                h2[j] = fma2(dA, h2[j], mul2(dx2, B2[t*8 + j]));
                if (j < 7) dA = mul2(dA, q);
            }
            dtv = ndt; xcv = nxc;
        }
        size_t base = ((size_t)(seq*8 + ck)*128 + d)*16;
        #pragma unroll
        for (int j = 0; j < 8; j++) {
            float lo, hi; unpack2(h2[j], lo, hi);
            g_pend[base + 2*j]   = lo;
            g_pend[base + 2*j+1] = hi;
        }
    } else {
        float h[16];
        #pragma unroll
        for (int s = 0; s < 16; s++) h[s] = 0.f;
        float dtv = dtp_[0], xcv = xcp_[0];
        for (int t = 0; t < 128; t++) {
            float ndt = 0.f, nxc = 0.f;
            if (t < 127) { ndt = dtp_[(t+1)*128]; nxc = xcp_[(t+1)*128]; }
            sdt += dtv;
            float dx = dtv * xcv;
            #pragma unroll
            for (int s = 0; s < 16; s++) {
                float dA = ex2f(dtv * a2[s]);
                h[s] = fmaf(dA, h[s], dx * Bs[t*16 + s]);
            }
            dtv = ndt; xcv = nxc;
        }
        size_t base = ((size_t)(seq*8 + ck)*128 + d)*16;
        #pragma unroll
        for (int s = 0; s < 16; s++) g_pend[base + s] = h[s];
    }
    size_t base = ((size_t)(seq*8 + ck)*128 + d)*16;
    #pragma unroll
    for (int s = 0; s < 16; s++) g_dtot[base + s] = ex2f(a2[s] * sdt);
}

// ============== K4: sequential combine of chunk states ======================
// grid = 256 (seq*8), block = 256; one thread per (seq, pair)
__global__ void __launch_bounds__(256) k4_combine()
{
    int blk = blockIdx.x;
    int seq = blk >> 3;
    int pair = (blk & 7) * 256 + threadIdx.x;
    float dtv[8], pev[8];
    #pragma unroll
    for (int k = 0; k < 8; k++) {
        size_t o = (size_t)(seq*8 + k)*2048 + pair;
        dtv[k] = g_dtot[o];
        pev[k] = g_pend[o];
    }
    float h = 0.f;
    #pragma unroll
    for (int k = 0; k < 8; k++) {
        g_h0[(size_t)(seq*8 + k)*2048 + pair] = h;
        h = fmaf(dtv[k], h, pev[k]);
    }
}

// ============== K5: full per-chunk scan + y epilogue ========================
// grid = 256, block = 128
__global__ void __launch_bounds__(128) k5_scan(
    const float* __restrict__ A_log, const float* __restrict__ Dp)
{
    __shared__ float Bs[128*16];
    __shared__ float Cs[128*16];
    int tid = threadIdx.x;
    int blk = blockIdx.x;
    int seq = blk >> 3;
    int ck  = blk & 7;
    int c0  = ck * 128;

    for (int idx = tid; idx < 2048; idx += 128) {
        Bs[idx] = g_Bm[(size_t)(seq*1024 + c0)*16 + idx];
        Cs[idx] = g_Cm[(size_t)(seq*1024 + c0)*16 + idx];
    }
    __syncthreads();

    int d = tid;
    float a2[16];
    #pragma unroll
    for (int s = 0; s < 16; s++) a2[s] = -__expf(A_log[d*16 + s]) * LOG2E;
    bool fast = ratio_fast(a2);
    float Dv = Dp[d];

    size_t hb = ((size_t)(seq*8 + ck)*128 + d)*16;
    const float* dtp_ = g_dt + (size_t)(seq*1024 + c0)*128 + d;
    const float* xcp_ = g_xc + (size_t)(seq*1024 + c0)*128 + d;
    const float* zp_  = g_z  + (size_t)(seq*1024 + c0)*128 + d;
    float*       yp_  = g_y  + (size_t)(seq*1024 + c0)*128 + d;

    if (fast) {
        const u64* B2 = (const u64*)Bs;
        const u64* C2 = (const u64*)Cs;
        u64 h2[8];
        #pragma unroll
        for (int j = 0; j < 8; j++) h2[j] = pack2(g_h0[hb + 2*j], g_h0[hb + 2*j + 1]);
        float dtv = dtp_[0], xcv = xcp_[0], zv = zp_[0];
        for (int t = 0; t < 128; t++) {
            float ndt = 0.f, nxc = 0.f, nz = 0.f;
            if (t < 127) { ndt = dtp_[(t+1)*128]; nxc = xcp_[(t+1)*128]; nz = zp_[(t+1)*128]; }
            float dx = dtv * xcv;
            u64 dx2 = pack2(dx, dx);
            float p = ex2f(dtv * a2[0]);
            float psq = p * p;
            u64 q  = pack2(psq, psq);
            u64 dA = pack2(p, psq);
            u64 y2 = 0ull;
            #pragma unroll
            for (int j = 0; j < 8; j++) {
                h2[j] = fma2(dA, h2[j], mul2(dx2, B2[t*8 + j]));
                y2 = fma2(h2[j], C2[t*8 + j], y2);
                if (j < 7) dA = mul2(dA, q);
            }
            float ylo, yhi; unpack2(y2, ylo, yhi);
            yp_[t*128] = (ylo + yhi + Dv*xcv) * siluf(zv);
            dtv = ndt; xcv = nxc; zv = nz;
        }
    } else {
        float h[16];
        #pragma unroll
        for (int s = 0; s < 16; s++) h[s] = g_h0[hb + s];
        float dtv = dtp_[0], xcv = xcp_[0], zv = zp_[0];
        for (int t = 0; t < 128; t++) {
            float ndt = 0.f, nxc = 0.f, nz = 0.f;
            if (t < 127) { ndt = dtp_[(t+1)*128]; nxc = xcp_[(t+1)*128]; nz = zp_[(t+1)*128]; }
            float dx = dtv * xcv;
            float y = 0.f;
            #pragma unroll
            for (int s = 0; s < 16; s++) {
                float dA = ex2f(dtv * a2[s]);
                h[s] = fmaf(dA, h[s], dx * Bs[t*16 + s]);
                y = fmaf(h[s], Cs[t*16 + s], y);
            }
            yp_[t*128] = (y + Dv*xcv) * siluf(zv);
            dtv = ndt; xcv = nxc; zv = nz;
        }
    }
}

// ============== K6: W_out GEMM + skip + transposed output ===================
// grid = 32 seq * 16 tiles (64 tokens), block = 128, dynamic smem
__global__ void __launch_bounds__(128) k6_outproj(
    const float* __restrict__ W_out, const float* __restrict__ skip,
    float* __restrict__ out)
{
    extern __shared__ float sm[];
    float* ys  = sm;                 // [64 t][130] (reused as os [64 c][65])
    float* Wsh = sm + 64*130;        // [64 c][130] (k contiguous)
    float* xns = Wsh + 64*130;       // [64 t][65 c]

    int tid = threadIdx.x;
    int blk = blockIdx.x;
    int seq = blk >> 4;
    int l0  = (blk & 15) * 64;
    int br  = seq >> 3;
    int b   = seq & 7;

    for (int idx = tid; idx < 64*128; idx += 128) {
        int t = idx >> 7, dd = idx & 127;
        ys[t*130 + dd] = g_y[(size_t)(seq*1024 + l0 + t)*128 + dd];
    }
    for (int idx = tid; idx < 64*128; idx += 128) {
        int c = idx >> 7, k = idx & 127;
        Wsh[c*130 + k] = W_out[(size_t)c*128 + k];
    }
    for (int idx = tid; idx < 64*64; idx += 128) {
        int t = idx >> 6, c = idx & 63;
        xns[t*65 + c] = g_xn[(size_t)(seq*1024 + l0 + t)*64 + c];
    }
    __syncthreads();

    int tg = tid >> 4;   // 8 token groups of 8 tokens
    int jg = tid & 15;   // outputs jg + 16u, u = 0..3
    u64 acc2[8][4];
    #pragma unroll
    for (int i = 0; i < 8; i++)
        #pragma unroll
        for (int u = 0; u < 4; u++) acc2[i][u] = 0ull;
    #pragma unroll 4
    for (int k2 = 0; k2 < 64; k2++) {
        u64 xv2[8], w2[4];
        #pragma unroll
        for (int i = 0; i < 8; i++)
            xv2[i] = *(const u64*)&ys[(tg*8 + i)*130 + 2*k2];
        #pragma unroll
        for (int u = 0; u < 4; u++)
            w2[u] = *(const u64*)&Wsh[(jg + 16*u)*130 + 2*k2];
        #pragma unroll
        for (int u = 0; u < 4; u++)
            #pragma unroll
            for (int i = 0; i < 8; i++)
                acc2[i][u] = fma2(xv2[i], w2[u], acc2[i][u]);
    }
    __syncthreads();
    float* os = ys;   // reuse: [c][t] pitch 65
    #pragma unroll
    for (int u = 0; u < 4; u++)
        #pragma unroll
        for (int i = 0; i < 8; i++) {
            float lo, hi; unpack2(acc2[i][u], lo, hi);
            os[(jg + 16*u)*65 + tg*8 + i] = lo + hi;
        }
    __syncthreads();
    float sk = skip[0];
    for (int idx = tid; idx < 4096; idx += 128) {
        int c = idx >> 6, t = idx & 63;
        out[(size_t)(b*256 + br*64 + c)*1024 + l0 + t] = os[c*65 + t] + sk * xns[t*65 + c];
    }
}

// ============================== launch ======================================
extern "C" void kernel_launch(void* const* d_in, const int* in_sizes, int n_in,
                              void* d_out, int out_size) {
    const float* x0      = (const float*)d_in[0];
    const float* x1      = (const float*)d_in[1];
    const float* x2      = (const float*)d_in[2];
    const float* x3      = (const float*)d_in[3];
    const float* g1      = (const float*)d_in[4];
    const float* be1     = (const float*)d_in[5];
    const float* g2      = (const float*)d_in[6];
    const float* be2     = (const float*)d_in[7];
    const float* g3      = (const float*)d_in[8];
    const float* be3     = (const float*)d_in[9];
    const float* g4      = (const float*)d_in[10];
    const float* be4     = (const float*)d_in[11];
    const float* skip    = (const float*)d_in[12];
    const float* W_in    = (const float*)d_in[13];
    const float* W_conv  = (const float*)d_in[14];
    const float* b_conv  = (const float*)d_in[15];
    const float* W_xproj = (const float*)d_in[16];
    const float* W_dt    = (const float*)d_in[17];
    const float* b_dt    = (const float*)d_in[18];
    const float* A_log   = (const float*)d_in[19];
    const float* Dp      = (const float*)d_in[20];
    const float* W_out   = (const float*)d_in[21];
    float* out = (float*)d_out;

    static bool configured = false;
    if (!configured) {
        cudaFuncSetAttribute(k6_outproj,
                             cudaFuncAttributeMaxDynamicSharedMemorySize,
                             (64*130 + 64*130 + 64*65) * (int)sizeof(float));
        configured = true;
    }

    k1_ln_inproj<<<1024, 128>>>(x0, x1, x2, x3, g1, g2, g3, g4,
                                be1, be2, be3, be4, W_in);
    k2_conv_proj<<<1024, 128>>>(W_conv, b_conv, W_xproj, W_dt, b_dt);
    k3_chunk<<<256, 128>>>(A_log);
    k4_combine<<<256, 256>>>();
    k5_scan<<<256, 128>>>(A_log, Dp);
    k6_outproj<<<512, 128, (64*130 + 64*130 + 64*65) * (int)sizeof(float)>>>(
        W_out, skip, out);
}

// round 4
// speedup vs baseline: 1.3786x; 1.3786x over previous
#include <cuda_runtime.h>
#include <cuda_bf16.h>

#define LOG2E 1.4426950408889634f
typedef unsigned long long u64;

#define NCHK 16
#define CHKL 64

// ---------------- scratch (__device__ globals; no allocation allowed) -------
__device__ float g_xn  [32*1024*64];
__device__ float g_xi  [32*1024*128];
__device__ float g_z   [32*1024*128];
__device__ float g_xc  [32*1024*128];
__device__ float g_dt  [32*1024*128];
__device__ float g_Bm  [32*1024*16];
__device__ float g_Cm  [32*1024*16];
__device__ float g_y   [32*1024*128];
__device__ float g_pend[32*NCHK*128*16];
__device__ float g_dtot[32*NCHK*128*16];
__device__ float g_h0  [32*NCHK*128*16];

__device__ __forceinline__ float ex2f(float x) {
    float r; asm("ex2.approx.f32 %0, %1;" : "=f"(r) : "f"(x)); return r;
}
__device__ __forceinline__ float siluf(float x) {
    return x / (1.0f + __expf(-x));
}

// ======================= K1: LayerNorm + W_in GEMM ==========================
// grid = 32 seq * 32 tiles (32 tokens each), block = 128  (R2 scalar tile)
__global__ void __launch_bounds__(128) k1_ln_inproj(
    const float* __restrict__ x0, const float* __restrict__ x1,
    const float* __restrict__ x2, const float* __restrict__ x3,
    const float* __restrict__ ga, const float* __restrict__ gb,
    const float* __restrict__ gc, const float* __restrict__ gd,
    const float* __restrict__ ba, const float* __restrict__ bb,
    const float* __restrict__ bc_, const float* __restrict__ bd,
    const float* __restrict__ W_in)
{
    __shared__ float xs[32*65];     // [t][c], pitch 65
    __shared__ float Wsh[128*65];   // [j][k], pitch 65 (one half of W_in)
    __shared__ float stat[64];

    int tid = threadIdx.x;
    int blk = blockIdx.x;
    int seq = blk >> 5;
    int l0  = (blk & 31) * 32;
    int br  = seq >> 3;
    int b   = seq & 7;

    const float* xp = (br == 0) ? x0 : (br == 1) ? x1 : (br == 2) ? x2 : x3;
    const float* gp = (br == 0) ? ga : (br == 1) ? gb : (br == 2) ? gc : gd;
    const float* bp = (br == 0) ? ba : (br == 1) ? bb : (br == 2) ? bc_ : bd;

    for (int idx = tid; idx < 2048; idx += 128) {
        int c = idx >> 5, t = idx & 31;
        xs[t*65 + c] = xp[(size_t)(b*64 + c)*1024 + l0 + t];
    }
    __syncthreads();
    if (tid < 32) {
        float s = 0.f, s2 = 0.f;
        #pragma unroll 8
        for (int c = 0; c < 64; c++) { float v = xs[tid*65 + c]; s += v; s2 += v*v; }
        float m = s * (1.0f/64.0f);
        float var = s2 * (1.0f/64.0f) - m*m;
        stat[tid*2]   = m;
        stat[tid*2+1] = rsqrtf(var + 1e-5f);
    }
    __syncthreads();
    for (int idx = tid; idx < 2048; idx += 128) {
        int c = idx & 63, t = idx >> 6;
        float v = (xs[t*65 + c] - stat[t*2]) * stat[t*2+1] * gp[c] + bp[c];
        xs[t*65 + c] = v;
        g_xn[(size_t)(seq*1024 + l0 + t)*64 + c] = v;
    }

    for (int h = 0; h < 2; h++) {
        __syncthreads();
        for (int idx = tid; idx < 8192; idx += 128) {
            int c = idx & 63, jj = idx >> 6;
            Wsh[jj*65 + c] = W_in[(size_t)(h*128 + jj)*64 + c];
        }
        __syncthreads();
        int tg = tid >> 5, jg = tid & 31;  // 4 token-groups x 32 outputs
        float acc[8][4];
        #pragma unroll
        for (int i = 0; i < 8; i++)
            #pragma unroll
            for (int u = 0; u < 4; u++) acc[i][u] = 0.f;
        #pragma unroll 4
        for (int k = 0; k < 64; k++) {
            float xv[8];
            #pragma unroll
            for (int i = 0; i < 8; i++) xv[i] = xs[(tg*8 + i)*65 + k];
            #pragma unroll
            for (int u = 0; u < 4; u++) {
                float w = Wsh[(jg + 32*u)*65 + k];
                #pragma unroll
                for (int i = 0; i < 8; i++) acc[i][u] = fmaf(xv[i], w, acc[i][u]);
            }
        }
        float* dst = (h == 0) ? g_xi : g_z;
        #pragma unroll
        for (int i = 0; i < 8; i++) {
            int t = tg*8 + i;
            #pragma unroll
            for (int u = 0; u < 4; u++)
                dst[(size_t)(seq*1024 + l0 + t)*128 + jg + 32*u] = acc[i][u];
        }
    }
}

// ============ K2: causal conv4 + SiLU + x_proj GEMM + dt(softplus) ==========
// grid = 32 seq * 32 tiles (32 tokens), block = 128 (thread = channel d)
__global__ void __launch_bounds__(128) k2_conv_proj(
    const float* __restrict__ W_conv, const float* __restrict__ b_conv,
    const float* __restrict__ W_xproj, const float* __restrict__ W_dt,
    const float* __restrict__ b_dt)
{
    __shared__ float bufA[37*128];
    __shared__ float xcs[32*128];
    __shared__ float res36[32*36];

    int tid = threadIdx.x;
    int blk = blockIdx.x;
    int seq = blk >> 5;
    int l0  = (blk & 31) * 32;

    for (int idx = tid; idx < 35*128; idx += 128) {
        int row = idx >> 7, dd = idx & 127;
        int tl = l0 - 3 + row;
        bufA[row*128 + dd] = (tl >= 0) ? g_xi[(size_t)(seq*1024 + tl)*128 + dd] : 0.f;
    }
    __syncthreads();

    int d = tid;
    float wc0 = W_conv[d*4+0], wc1 = W_conv[d*4+1], wc2 = W_conv[d*4+2], wc3 = W_conv[d*4+3];
    float bcv = b_conv[d];
    #pragma unroll 4
    for (int t = 0; t < 32; t++) {
        float v = bcv + wc0*bufA[t*128 + d] + wc1*bufA[(t+1)*128 + d]
                      + wc2*bufA[(t+2)*128 + d] + wc3*bufA[(t+3)*128 + d];
        v = siluf(v);
        xcs[t*128 + d] = v;
        g_xc[(size_t)(seq*1024 + l0 + t)*128 + d] = v;
    }
    __syncthreads();
    for (int idx = tid; idx < 36*128; idx += 128) {
        int dd = idx & 127, j = idx >> 7;
        bufA[dd*37 + j] = W_xproj[(size_t)j*128 + dd];
    }
    __syncthreads();
    for (int p = tid; p < 576; p += 128) {
        int tok = p / 18;
        int j0 = (p - tok*18) * 2;
        float a0 = 0.f, a1 = 0.f;
        #pragma unroll 16
        for (int dd = 0; dd < 128; dd++) {
            float xv = xcs[tok*128 + dd];
            a0 = fmaf(xv, bufA[dd*37 + j0],     a0);
            a1 = fmaf(xv, bufA[dd*37 + j0 + 1], a1);
        }
        res36[tok*36 + j0]     = a0;
        res36[tok*36 + j0 + 1] = a1;
    }
    __syncthreads();
    float wd0 = W_dt[d*4+0], wd1 = W_dt[d*4+1], wd2 = W_dt[d*4+2], wd3 = W_dt[d*4+3];
    float bdv = b_dt[d];
    #pragma unroll 4
    for (int t = 0; t < 32; t++) {
        float raw = bdv + wd0*res36[t*36+0] + wd1*res36[t*36+1]
                        + wd2*res36[t*36+2] + wd3*res36[t*36+3];
        float sp = fmaxf(raw, 0.f) + log1pf(__expf(-fabsf(raw)));
        g_dt[(size_t)(seq*1024 + l0 + t)*128 + d] = sp;
    }
    for (int idx = tid; idx < 1024; idx += 128) {
        int tok = idx >> 5, q = idx & 31;
        float v = res36[tok*36 + 4 + q];
        if (q < 16) g_Bm[(size_t)(seq*1024 + l0 + tok)*16 + q]        = v;
        else        g_Cm[(size_t)(seq*1024 + l0 + tok)*16 + (q - 16)] = v;
    }
}

// helper: detect a2[s] == (s+1)*a2[0] (true for this problem's A_log)
__device__ __forceinline__ bool ratio_fast(const float* a2) {
    bool ok = true;
    #pragma unroll
    for (int s = 1; s < 16; s++) {
        float want = (float)(s + 1) * a2[0];
        ok = ok && (fabsf(a2[s] - want) <= 1e-3f * fabsf(want));
    }
    return ok;
}

// compute dA[0..15] = p^(s+1) with a log-depth ladder (scalar, 1 ex2 total)
__device__ __forceinline__ void powers16(float p, float* dA) {
    dA[0] = p;
    dA[1] = p * p;
    #pragma unroll
    for (int s = 2; s < 16; s++) dA[s] = dA[s >> 1] * dA[(s + 1) >> 1];
}

// ============== K3: per-chunk scan summaries (h0 = 0) =======================
// grid = 512 (seq*NCHK + chunk), block = 128 (thread = channel d)
__global__ void __launch_bounds__(128) k3_chunk(const float* __restrict__ A_log)
{
    __shared__ float Bs[CHKL*16];
    int tid = threadIdx.x;
    int blk = blockIdx.x;
    int seq = blk >> 4;
    int ck  = blk & (NCHK-1);
    int c0  = ck * CHKL;

    for (int idx = tid; idx < CHKL*16; idx += 128)
        Bs[idx] = g_Bm[(size_t)(seq*1024 + c0)*16 + idx];
    __syncthreads();

    int d = tid;
    float a2[16];
    #pragma unroll
    for (int s = 0; s < 16; s++) a2[s] = -__expf(A_log[d*16 + s]) * LOG2E;
    bool fast = ratio_fast(a2);

    const float* dtp_ = g_dt + (size_t)(seq*1024 + c0)*128 + d;
    const float* xcp_ = g_xc + (size_t)(seq*1024 + c0)*128 + d;
    float sdt = 0.f;
    float h[16];
    #pragma unroll
    for (int s = 0; s < 16; s++) h[s] = 0.f;

    float dtv = dtp_[0], xcv = xcp_[0];
    if (fast) {
        for (int t = 0; t < CHKL; t++) {
            float ndt = 0.f, nxc = 0.f;
            if (t < CHKL-1) { ndt = dtp_[(t+1)*128]; nxc = xcp_[(t+1)*128]; }
            sdt += dtv;
            float dx = dtv * xcv;
            float p = ex2f(dtv * a2[0]);
            float dA[16]; powers16(p, dA);
            #pragma unroll
            for (int s = 0; s < 16; s++)
                h[s] = fmaf(dA[s], h[s], dx * Bs[t*16 + s]);
            dtv = ndt; xcv = nxc;
        }
    } else {
        for (int t = 0; t < CHKL; t++) {
            float ndt = 0.f, nxc = 0.f;
            if (t < CHKL-1) { ndt = dtp_[(t+1)*128]; nxc = xcp_[(t+1)*128]; }
            sdt += dtv;
            float dx = dtv * xcv;
            #pragma unroll
            for (int s = 0; s < 16; s++) {
                float dA = ex2f(dtv * a2[s]);
                h[s] = fmaf(dA, h[s], dx * Bs[t*16 + s]);
            }
            dtv = ndt; xcv = nxc;
        }
    }
    size_t base = ((size_t)(seq*NCHK + ck)*128 + d)*16;
    #pragma unroll
    for (int s = 0; s < 16; s++) {
        g_pend[base + s] = h[s];
        g_dtot[base + s] = ex2f(a2[s] * sdt);
    }
}

// ============== K4: sequential combine of chunk states ======================
// grid = 256 (seq*8), block = 256; one thread per (seq, pair)
__global__ void __launch_bounds__(256) k4_combine()
{
    int blk = blockIdx.x;
    int seq = blk >> 3;
    int pair = (blk & 7) * 256 + threadIdx.x;
    float dtv[NCHK], pev[NCHK];
    #pragma unroll
    for (int k = 0; k < NCHK; k++) {
        size_t o = (size_t)(seq*NCHK + k)*2048 + pair;
        dtv[k] = g_dtot[o];
        pev[k] = g_pend[o];
    }
    float h = 0.f;
    #pragma unroll
    for (int k = 0; k < NCHK; k++) {
        g_h0[(size_t)(seq*NCHK + k)*2048 + pair] = h;
        h = fmaf(dtv[k], h, pev[k]);
    }
}

// ============== K5: full per-chunk scan + y epilogue ========================
// grid = 512, block = 128
__global__ void __launch_bounds__(128) k5_scan(
    const float* __restrict__ A_log, const float* __restrict__ Dp)
{
    __shared__ float Bs[CHKL*16];
    __shared__ float Cs[CHKL*16];
    int tid = threadIdx.x;
    int blk = blockIdx.x;
    int seq = blk >> 4;
    int ck  = blk & (NCHK-1);
    int c0  = ck * CHKL;

    for (int idx = tid; idx < CHKL*16; idx += 128) {
        Bs[idx] = g_Bm[(size_t)(seq*1024 + c0)*16 + idx];
        Cs[idx] = g_Cm[(size_t)(seq*1024 + c0)*16 + idx];
    }
    __syncthreads();

    int d = tid;
    float a2[16];
    #pragma unroll
    for (int s = 0; s < 16; s++) a2[s] = -__expf(A_log[d*16 + s]) * LOG2E;
    bool fast = ratio_fast(a2);
    float Dv = Dp[d];

    float h[16];
    size_t hb = ((size_t)(seq*NCHK + ck)*128 + d)*16;
    #pragma unroll
    for (int s = 0; s < 16; s++) h[s] = g_h0[hb + s];

    const float* dtp_ = g_dt + (size_t)(seq*1024 + c0)*128 + d;
    const float* xcp_ = g_xc + (size_t)(seq*1024 + c0)*128 + d;
    const float* zp_  = g_z  + (size_t)(seq*1024 + c0)*128 + d;
    float*       yp_  = g_y  + (size_t)(seq*1024 + c0)*128 + d;

    float dtv = dtp_[0], xcv = xcp_[0], zv = zp_[0];
    if (fast) {
        for (int t = 0; t < CHKL; t++) {
            float ndt = 0.f, nxc = 0.f, nz = 0.f;
            if (t < CHKL-1) { ndt = dtp_[(t+1)*128]; nxc = xcp_[(t+1)*128]; nz = zp_[(t+1)*128]; }
            float dx = dtv * xcv;
            float p = ex2f(dtv * a2[0]);
            float dA[16]; powers16(p, dA);
            float y = 0.f;
            #pragma unroll
            for (int s = 0; s < 16; s++) {
                h[s] = fmaf(dA[s], h[s], dx * Bs[t*16 + s]);
                y = fmaf(h[s], Cs[t*16 + s], y);
            }
            yp_[t*128] = (y + Dv*xcv) * siluf(zv);
            dtv = ndt; xcv = nxc; zv = nz;
        }
    } else {
        for (int t = 0; t < CHKL; t++) {
            float ndt = 0.f, nxc = 0.f, nz = 0.f;
            if (t < CHKL-1) { ndt = dtp_[(t+1)*128]; nxc = xcp_[(t+1)*128]; nz = zp_[(t+1)*128]; }
            float dx = dtv * xcv;
            float y = 0.f;
            #pragma unroll
            for (int s = 0; s < 16; s++) {
                float dA = ex2f(dtv * a2[s]);
                h[s] = fmaf(dA, h[s], dx * Bs[t*16 + s]);
                y = fmaf(h[s], Cs[t*16 + s], y);
            }
            yp_[t*128] = (y + Dv*xcv) * siluf(zv);
            dtv = ndt; xcv = nxc; zv = nz;
        }
    }
}

// ============== K6: W_out GEMM + skip + transposed output ===================
// grid = 32 seq * 16 tiles (64 tokens), block = 128, dynamic smem (R2 scalar)
__global__ void __launch_bounds__(128) k6_outproj(
    const float* __restrict__ W_out, const float* __restrict__ skip,
    float* __restrict__ out)
{
    extern __shared__ float sm[];
    float* ys  = sm;                 // [64 t][129] (reused as os [64 c][65])
    float* Wsh = sm + 64*129;        // [128 k][65 c]
    float* xns = Wsh + 128*65;       // [64 t][65 c]

    int tid = threadIdx.x;
    int blk = blockIdx.x;
    int seq = blk >> 4;
    int l0  = (blk & 15) * 64;
    int br  = seq >> 3;
    int b   = seq & 7;

    for (int idx = tid; idx < 64*128; idx += 128) {
        int t = idx >> 7, dd = idx & 127;
        ys[t*129 + dd] = g_y[(size_t)(seq*1024 + l0 + t)*128 + dd];
    }
    for (int idx = tid; idx < 64*128; idx += 128) {
        int c = idx >> 7, k = idx & 127;
        Wsh[k*65 + c] = W_out[(size_t)c*128 + k];
    }
    for (int idx = tid; idx < 64*64; idx += 128) {
        int t = idx >> 6, c = idx & 63;
        xns[t*65 + c] = g_xn[(size_t)(seq*1024 + l0 + t)*64 + c];
    }
    __syncthreads();

    int tg = tid >> 4, jg = tid & 15;   // 8 token-groups x 16 outputs (jg+16u)
    float acc[8][4];
    #pragma unroll
    for (int i = 0; i < 8; i++)
        #pragma unroll
        for (int u = 0; u < 4; u++) acc[i][u] = 0.f;
    #pragma unroll 4
    for (int k = 0; k < 128; k++) {
        float xv[8];
        #pragma unroll
        for (int i = 0; i < 8; i++) xv[i] = ys[(tg*8 + i)*129 + k];
        #pragma unroll
        for (int u = 0; u < 4; u++) {
            float w = Wsh[k*65 + jg + 16*u];
            #pragma unroll
            for (int i = 0; i < 8; i++) acc[i][u] = fmaf(xv[i], w, acc[i][u]);
        }
    }
    __syncthreads();
    float* os = ys;   // reuse: [c][t] pitch 65
    #pragma unroll
    for (int u = 0; u < 4; u++)
        #pragma unroll
        for (int i = 0; i < 8; i++)
            os[(jg + 16*u)*65 + tg*8 + i] = acc[i][u];
    __syncthreads();
    float sk = skip[0];
    for (int idx = tid; idx < 4096; idx += 128) {
        int c = idx >> 6, t = idx & 63;
        out[(size_t)(b*256 + br*64 + c)*1024 + l0 + t] = os[c*65 + t] + sk * xns[t*65 + c];
    }
}

// ============================== launch ======================================
extern "C" void kernel_launch(void* const* d_in, const int* in_sizes, int n_in,
                              void* d_out, int out_size) {
    const float* x0      = (const float*)d_in[0];
    const float* x1      = (const float*)d_in[1];
    const float* x2      = (const float*)d_in[2];
    const float* x3      = (const float*)d_in[3];
    const float* g1      = (const float*)d_in[4];
    const float* be1     = (const float*)d_in[5];
    const float* g2      = (const float*)d_in[6];
    const float* be2     = (const float*)d_in[7];
    const float* g3      = (const float*)d_in[8];
    const float* be3     = (const float*)d_in[9];
    const float* g4      = (const float*)d_in[10];
    const float* be4     = (const float*)d_in[11];
    const float* skip    = (const float*)d_in[12];
    const float* W_in    = (const float*)d_in[13];
    const float* W_conv  = (const float*)d_in[14];
    const float* b_conv  = (const float*)d_in[15];
    const float* W_xproj = (const float*)d_in[16];
    const float* W_dt    = (const float*)d_in[17];
    const float* b_dt    = (const float*)d_in[18];
    const float* A_log   = (const float*)d_in[19];
    const float* Dp      = (const float*)d_in[20];
    const float* W_out   = (const float*)d_in[21];
    float* out = (float*)d_out;

    static bool configured = false;
    if (!configured) {
        cudaFuncSetAttribute(k6_outproj,
                             cudaFuncAttributeMaxDynamicSharedMemorySize,
                             (64*129 + 128*65 + 64*65) * (int)sizeof(float));
        configured = true;
    }

    k1_ln_inproj<<<1024, 128>>>(x0, x1, x2, x3, g1, g2, g3, g4,
                                be1, be2, be3, be4, W_in);
    k2_conv_proj<<<1024, 128>>>(W_conv, b_conv, W_xproj, W_dt, b_dt);
    k3_chunk<<<512, 128>>>(A_log);
    k4_combine<<<256, 256>>>();
    k5_scan<<<512, 128>>>(A_log, Dp);
    k6_outproj<<<512, 128, (64*129 + 128*65 + 64*65) * (int)sizeof(float)>>>(
        W_out, skip, out);
}